// round 6
// baseline (speedup 1.0000x reference)
#include <cuda_runtime.h>
#include <math.h>

#define BB 32
#define HH 16
#define KVN 8192
#define DHD 64
#define DM 1024
#define SPLITS 8
#define WARPS_PER_BLK 8
#define NPART (SPLITS * WARPS_PER_BLK)          /* 64 partials per (b,h) */
#define ROWS_PER_WARP (KVN / NPART)             /* 128 */

__device__ float g_qkv[BB * 3 * DM];            /* [B][3D] */
__device__ float g_pm[BB * HH * NPART];
__device__ float g_pl[BB * HH * NPART];
__device__ float g_pacc[(size_t)BB * HH * NPART * DHD];  /* 8 MB */
__device__ float g_ctx[BB * DM];

/* ---------------- QKV projection: qkv[b, j] = x[b,:] @ W[:, j] + bias[j] -------- */
__global__ void qkv_kernel(const float* __restrict__ x,
                           const float* __restrict__ w,
                           const float* __restrict__ bias) {
    __shared__ float xs[DM];
    const int b = blockIdx.y;
    const int tid = threadIdx.x;
    for (int i = tid; i < DM / 4; i += blockDim.x)
        ((float4*)xs)[i] = ((const float4*)(x + (size_t)b * DM))[i];
    __syncthreads();

    const int j = blockIdx.x * 1024 + tid * 4;   /* grid.x = 3 -> covers 3072 cols */
    float4 a0 = {0.f,0.f,0.f,0.f}, a1 = {0.f,0.f,0.f,0.f};
    float4 a2 = {0.f,0.f,0.f,0.f}, a3 = {0.f,0.f,0.f,0.f};
    #pragma unroll 4
    for (int i = 0; i < DM; i += 4) {
        float x0 = xs[i], x1 = xs[i+1], x2 = xs[i+2], x3 = xs[i+3];
        float4 w0 = *(const float4*)(w + (size_t)(i  ) * 3072 + j);
        float4 w1 = *(const float4*)(w + (size_t)(i+1) * 3072 + j);
        float4 w2 = *(const float4*)(w + (size_t)(i+2) * 3072 + j);
        float4 w3 = *(const float4*)(w + (size_t)(i+3) * 3072 + j);
        a0.x += x0*w0.x; a0.y += x0*w0.y; a0.z += x0*w0.z; a0.w += x0*w0.w;
        a1.x += x1*w1.x; a1.y += x1*w1.y; a1.z += x1*w1.z; a1.w += x1*w1.w;
        a2.x += x2*w2.x; a2.y += x2*w2.y; a2.z += x2*w2.z; a2.w += x2*w2.w;
        a3.x += x3*w3.x; a3.y += x3*w3.y; a3.z += x3*w3.z; a3.w += x3*w3.w;
    }
    float4 bv = *(const float4*)(bias + j);
    float4 r;
    r.x = a0.x + a1.x + a2.x + a3.x + bv.x;
    r.y = a0.y + a1.y + a2.y + a3.y + bv.y;
    r.z = a0.z + a1.z + a2.z + a3.z + bv.z;
    r.w = a0.w + a1.w + a2.w + a3.w + bv.w;
    *(float4*)(g_qkv + (size_t)b * 3 * DM + j) = r;
}

/* ---------------- Split-KV attention over the cache ---------------------------- */
/* grid (SPLITS, H, B), block 256. Warp w handles 128 consecutive KV rows.         */
__global__ void attn_kernel(const float* __restrict__ Kc,
                            const float* __restrict__ Vc) {
    const int split = blockIdx.x, h = blockIdx.y, b = blockIdx.z;
    const int warp = threadIdx.x >> 5, lane = threadIdx.x & 31;
    const int bh = b * HH + h;

    const float2 q2 = ((const float2*)(g_qkv + (size_t)b * 3 * DM + h * DHD))[lane];

    const int row0 = split * (KVN / SPLITS) + warp * ROWS_PER_WARP;
    const float2* Kp = (const float2*)(Kc + ((size_t)bh * KVN + row0) * DHD);
    const float2* Vp = (const float2*)(Vc + ((size_t)bh * KVN + row0) * DHD);

    float m = -INFINITY, l = 0.f, ax = 0.f, ay = 0.f;

    for (int it = 0; it < ROWS_PER_WARP / 8; it++) {
        float s[8];
        #pragma unroll
        for (int r = 0; r < 8; r++) {
            float2 k2 = Kp[(it * 8 + r) * 32 + lane];
            float p = q2.x * k2.x + q2.y * k2.y;
            p += __shfl_xor_sync(0xffffffffu, p, 16);
            p += __shfl_xor_sync(0xffffffffu, p, 8);
            p += __shfl_xor_sync(0xffffffffu, p, 4);
            p += __shfl_xor_sync(0xffffffffu, p, 2);
            p += __shfl_xor_sync(0xffffffffu, p, 1);
            s[r] = p;
        }
        float tmax = s[0];
        #pragma unroll
        for (int r = 1; r < 8; r++) tmax = fmaxf(tmax, s[r]);
        const float mn = fmaxf(m, tmax);
        const float corr = __expf(m - mn);
        l *= corr; ax *= corr; ay *= corr;
        #pragma unroll
        for (int r = 0; r < 8; r++) {
            float e = __expf(s[r] - mn);
            l += e;
            float2 v2 = Vp[(it * 8 + r) * 32 + lane];
            ax += e * v2.x;
            ay += e * v2.y;
        }
        m = mn;
    }

    const int part = split * WARPS_PER_BLK + warp;
    float* ap = g_pacc + ((size_t)bh * NPART + part) * DHD;
    ((float2*)ap)[lane] = make_float2(ax, ay);
    if (lane == 0) {
        g_pm[bh * NPART + part] = m;
        g_pl[bh * NPART + part] = l;
    }
}

/* ---------------- Combine partials + fold in current token --------------------- */
__global__ void combine_kernel() {
    const int bh = blockIdx.x;
    const int b = bh / HH, h = bh % HH;
    const int tid = threadIdx.x;  /* 0..63 = head dim */

    __shared__ float ms[NPART], ls[NPART], red[64];
    ms[tid] = g_pm[bh * NPART + tid];
    ls[tid] = g_pl[bh * NPART + tid];
    __syncthreads();

    float M = ms[0];
    #pragma unroll 8
    for (int p = 1; p < NPART; p++) M = fmaxf(M, ms[p]);

    float num = 0.f, den = 0.f;
    const float* ap = g_pacc + (size_t)bh * NPART * DHD;
    #pragma unroll 4
    for (int p = 0; p < NPART; p++) {
        float wgt = __expf(ms[p] - M);
        num += wgt * ap[p * DHD + tid];
        den += wgt * ls[p];
    }

    const float qd = g_qkv[(size_t)b * 3 * DM +            h * DHD + tid];
    const float kd = g_qkv[(size_t)b * 3 * DM + DM      +  h * DHD + tid];
    const float vd = g_qkv[(size_t)b * 3 * DM + 2 * DM  +  h * DHD + tid];

    red[tid] = qd * kd;
    for (int off = 32; off > 0; off >>= 1) {
        __syncthreads();
        if (tid < off) red[tid] += red[tid + off];
    }
    __syncthreads();
    const float scur = red[0];

    const float Mn = fmaxf(M, scur);
    const float sc = __expf(M - Mn);
    const float ec = __expf(scur - Mn);
    const float ctx = (num * sc + ec * vd) / fmaxf(den * sc + ec, 1e-9f);
    g_ctx[(size_t)b * DM + h * DHD + tid] = ctx;
}

/* ---------------- Output projection -------------------------------------------- */
__global__ void proj_kernel(const float* __restrict__ w,
                            const float* __restrict__ bias,
                            float* __restrict__ out) {
    __shared__ float xs[DM];
    const int b = blockIdx.y;
    const int tid = threadIdx.x;
    for (int i = tid; i < DM / 4; i += blockDim.x)
        ((float4*)xs)[i] = ((const float4*)(g_ctx + (size_t)b * DM))[i];
    __syncthreads();

    const int j = blockIdx.x * 256 + tid;   /* grid.x = 4 -> 1024 cols */
    float a0 = 0.f, a1 = 0.f, a2 = 0.f, a3 = 0.f;
    #pragma unroll 4
    for (int i = 0; i < DM; i += 4) {
        a0 += xs[i  ] * w[(size_t)(i  ) * DM + j];
        a1 += xs[i+1] * w[(size_t)(i+1) * DM + j];
        a2 += xs[i+2] * w[(size_t)(i+2) * DM + j];
        a3 += xs[i+3] * w[(size_t)(i+3) * DM + j];
    }
    out[(size_t)b * DM + j] = a0 + a1 + a2 + a3 + bias[j];
}

extern "C" void kernel_launch(void* const* d_in, const int* in_sizes, int n_in,
                              void* d_out, int out_size) {
    const float* hs = (const float*)d_in[0];
    const float* kc = (const float*)d_in[1];
    const float* vc = (const float*)d_in[2];
    const float* wa = (const float*)d_in[3];
    const float* ba = (const float*)d_in[4];
    const float* wp = (const float*)d_in[5];
    const float* bp = (const float*)d_in[6];
    float* out = (float*)d_out;

    qkv_kernel<<<dim3(3, BB), 256>>>(hs, wa, ba);
    attn_kernel<<<dim3(SPLITS, HH, BB), 256>>>(kc, vc);
    combine_kernel<<<BB * HH, 64>>>();
    proj_kernel<<<dim3(4, BB), 256>>>(wp, bp, out);
}

// round 8
// speedup vs baseline: 1.4450x; 1.4450x over previous
#include <cuda_runtime.h>
#include <math.h>

#define BB 32
#define HH 16
#define KVN 8192
#define DHD 64
#define DM 1024
#define SPLITS 8
#define WARPS_PER_BLK 8
#define NPART (SPLITS * WARPS_PER_BLK)          /* 64 partials per (b,h) */
#define ROWS_PER_WARP (KVN / NPART)             /* 128 */
#define IC 8                                     /* i-chunks for batched GEMV */

__device__ float g_qkv[BB * 3 * DM];             /* [B][3D] */
__device__ float g_qkv_part[IC * BB * 3 * DM];   /* 3 MB */
__device__ float g_proj_part[IC * BB * DM];      /* 1 MB */
__device__ float g_pm[BB * HH * NPART];
__device__ float g_pl[BB * HH * NPART];
__device__ float g_pacc[(size_t)BB * HH * NPART * DHD];  /* 8 MB */
__device__ float g_ctx[BB * DM];

/* ============ Batched QKV GEMV: weight read ONCE, reused across all 32 b ======= */
/* grid (24 j-tiles, 8 i-chunks), 128 threads. Thread owns column j, 32 b-accums. */
__global__ void qkv_part_kernel(const float* __restrict__ x,
                                const float* __restrict__ w) {
    __shared__ float xs[128 * 33];               /* [i][b], pad 33: conflict-free */
    const int tid = threadIdx.x;
    const int j = blockIdx.x * 128 + tid;
    const int i0 = blockIdx.y * 128;

    for (int idx = tid; idx < BB * 128; idx += 128) {
        const int bb = idx >> 7, ii = idx & 127;
        xs[ii * 33 + bb] = x[bb * DM + i0 + ii];
    }
    __syncthreads();

    float acc[BB];
    #pragma unroll
    for (int bb = 0; bb < BB; bb++) acc[bb] = 0.f;

    const float* wp = w + (size_t)i0 * (3 * DM) + j;
    #pragma unroll 4
    for (int i = 0; i < 128; i++) {
        const float wv = wp[(size_t)i * (3 * DM)];
        #pragma unroll
        for (int bb = 0; bb < BB; bb++) acc[bb] += xs[i * 33 + bb] * wv;
    }

    float* op = g_qkv_part + (size_t)blockIdx.y * BB * 3 * DM + j;
    #pragma unroll
    for (int bb = 0; bb < BB; bb++) op[(size_t)bb * 3 * DM] = acc[bb];
}

__global__ void qkv_reduce_kernel(const float* __restrict__ bias) {
    const int idx = blockIdx.x * 256 + threadIdx.x;   /* 32*3072 elems */
    const int j = idx % (3 * DM);
    float s = bias[j];
    #pragma unroll
    for (int ic = 0; ic < IC; ic++)
        s += g_qkv_part[(size_t)ic * BB * 3 * DM + idx];
    g_qkv[idx] = s;
}

/* ---------------- Split-KV attention over the cache ---------------------------- */
__global__ void attn_kernel(const float* __restrict__ Kc,
                            const float* __restrict__ Vc) {
    const int split = blockIdx.x, h = blockIdx.y, b = blockIdx.z;
    const int warp = threadIdx.x >> 5, lane = threadIdx.x & 31;
    const int bh = b * HH + h;

    const float2 q2 = ((const float2*)(g_qkv + (size_t)b * 3 * DM + h * DHD))[lane];

    const int row0 = split * (KVN / SPLITS) + warp * ROWS_PER_WARP;
    const float2* Kp = (const float2*)(Kc + ((size_t)bh * KVN + row0) * DHD);
    const float2* Vp = (const float2*)(Vc + ((size_t)bh * KVN + row0) * DHD);

    float m = -INFINITY, l = 0.f, ax = 0.f, ay = 0.f;

    for (int it = 0; it < ROWS_PER_WARP / 8; it++) {
        float s[8];
        #pragma unroll
        for (int r = 0; r < 8; r++) {
            float2 k2 = __ldcs(&Kp[(it * 8 + r) * 32 + lane]);
            float p = q2.x * k2.x + q2.y * k2.y;
            p += __shfl_xor_sync(0xffffffffu, p, 16);
            p += __shfl_xor_sync(0xffffffffu, p, 8);
            p += __shfl_xor_sync(0xffffffffu, p, 4);
            p += __shfl_xor_sync(0xffffffffu, p, 2);
            p += __shfl_xor_sync(0xffffffffu, p, 1);
            s[r] = p;
        }
        float tmax = s[0];
        #pragma unroll
        for (int r = 1; r < 8; r++) tmax = fmaxf(tmax, s[r]);
        const float mn = fmaxf(m, tmax);
        const float corr = __expf(m - mn);
        l *= corr; ax *= corr; ay *= corr;
        #pragma unroll
        for (int r = 0; r < 8; r++) {
            float e = __expf(s[r] - mn);
            l += e;
            float2 v2 = __ldcs(&Vp[(it * 8 + r) * 32 + lane]);
            ax += e * v2.x;
            ay += e * v2.y;
        }
        m = mn;
    }

    const int part = split * WARPS_PER_BLK + warp;
    float* ap = g_pacc + ((size_t)bh * NPART + part) * DHD;
    ((float2*)ap)[lane] = make_float2(ax, ay);
    if (lane == 0) {
        g_pm[bh * NPART + part] = m;
        g_pl[bh * NPART + part] = l;
    }
}

/* ---------------- Combine partials + fold in current token --------------------- */
__global__ void combine_kernel() {
    const int bh = blockIdx.x;
    const int b = bh / HH, h = bh % HH;
    const int tid = threadIdx.x;  /* 0..63 = head dim */

    __shared__ float ms[NPART], ls[NPART], red[64];
    ms[tid] = g_pm[bh * NPART + tid];
    ls[tid] = g_pl[bh * NPART + tid];
    __syncthreads();

    float M = ms[0];
    #pragma unroll 8
    for (int p = 1; p < NPART; p++) M = fmaxf(M, ms[p]);

    float num = 0.f, den = 0.f;
    const float* ap = g_pacc + (size_t)bh * NPART * DHD;
    #pragma unroll 4
    for (int p = 0; p < NPART; p++) {
        float wgt = __expf(ms[p] - M);
        num += wgt * ap[p * DHD + tid];
        den += wgt * ls[p];
    }

    const float qd = g_qkv[(size_t)b * 3 * DM +            h * DHD + tid];
    const float kd = g_qkv[(size_t)b * 3 * DM + DM      +  h * DHD + tid];
    const float vd = g_qkv[(size_t)b * 3 * DM + 2 * DM  +  h * DHD + tid];

    red[tid] = qd * kd;
    for (int off = 32; off > 0; off >>= 1) {
        __syncthreads();
        if (tid < off) red[tid] += red[tid + off];
    }
    __syncthreads();
    const float scur = red[0];

    const float Mn = fmaxf(M, scur);
    const float sc = __expf(M - Mn);
    const float ec = __expf(scur - Mn);
    const float ctx = (num * sc + ec * vd) / fmaxf(den * sc + ec, 1e-9f);
    g_ctx[(size_t)b * DM + h * DHD + tid] = ctx;
}

/* ============ Batched output projection: weight read ONCE ====================== */
/* grid (8 j-tiles, 8 i-chunks), 128 threads. */
__global__ void proj_part_kernel(const float* __restrict__ w) {
    __shared__ float xs[128 * 33];
    const int tid = threadIdx.x;
    const int j = blockIdx.x * 128 + tid;
    const int i0 = blockIdx.y * 128;

    for (int idx = tid; idx < BB * 128; idx += 128) {
        const int bb = idx >> 7, ii = idx & 127;
        xs[ii * 33 + bb] = g_ctx[bb * DM + i0 + ii];
    }
    __syncthreads();

    float acc[BB];
    #pragma unroll
    for (int bb = 0; bb < BB; bb++) acc[bb] = 0.f;

    const float* wp = w + (size_t)i0 * DM + j;
    #pragma unroll 4
    for (int i = 0; i < 128; i++) {
        const float wv = wp[(size_t)i * DM];
        #pragma unroll
        for (int bb = 0; bb < BB; bb++) acc[bb] += xs[i * 33 + bb] * wv;
    }

    float* op = g_proj_part + (size_t)blockIdx.y * BB * DM + j;
    #pragma unroll
    for (int bb = 0; bb < BB; bb++) op[(size_t)bb * DM] = acc[bb];
}

__global__ void proj_reduce_kernel(const float* __restrict__ bias,
                                   float* __restrict__ out) {
    const int idx = blockIdx.x * 256 + threadIdx.x;   /* 32*1024 elems */
    const int j = idx % DM;
    float s = bias[j];
    #pragma unroll
    for (int ic = 0; ic < IC; ic++)
        s += g_proj_part[(size_t)ic * BB * DM + idx];
    out[idx] = s;
}

extern "C" void kernel_launch(void* const* d_in, const int* in_sizes, int n_in,
                              void* d_out, int out_size) {
    const float* hs = (const float*)d_in[0];
    const float* kc = (const float*)d_in[1];
    const float* vc = (const float*)d_in[2];
    const float* wa = (const float*)d_in[3];
    const float* ba = (const float*)d_in[4];
    const float* wp = (const float*)d_in[5];
    const float* bp = (const float*)d_in[6];
    float* out = (float*)d_out;

    qkv_part_kernel<<<dim3(3 * DM / 128, IC), 128>>>(hs, wa);
    qkv_reduce_kernel<<<BB * 3 * DM / 256, 256>>>(ba);
    attn_kernel<<<dim3(SPLITS, HH, BB), 256>>>(kc, vc);
    combine_kernel<<<BB * HH, 64>>>();
    proj_part_kernel<<<dim3(DM / 128, IC), 128>>>(wp);
    proj_reduce_kernel<<<BB * DM / 256, 256>>>(bp, out);
}